// round 2
// baseline (speedup 1.0000x reference)
#include <cuda_runtime.h>
#include <math.h>

#define Bn 2
#define Ln 2048
#define Dn 512
#define Nn 4096
#define Gn 64
#define Tn 512
#define EPSN 1e-12f
#define EPSW 1e-8f
#define NT 512
#define NW 16

// ---------------- scratch (static device globals; no allocation) ----------------
__device__ __align__(256) float g_gn[Bn * Ln * Gn];   // unit group vectors, token storage
__device__ float g_norms[Bn * Ln];
__device__ float g_sim[Bn * Ln];                      // round-1 adjacent sims
__device__ float g_coef[Bn * Ln];                     // per-original-token x coefficient
__device__ int   g_lo[Bn * (Tn + 1)];                 // final slot range starts

// ---------------- K1: g = x @ w^T, norms, gn ----------------
// 64 threads (2 warps) per block, 4 tokens per block, 2 groups per inner iter
// (8 independent shuffle-reduce chains to hide SHFL latency).
__global__ void k_gn(const float* __restrict__ x, const float* __restrict__ w)
{
    int tok0 = blockIdx.x * 4;
    int warp = threadIdx.x >> 5;
    int lane = threadIdx.x & 31;

    float4 xr[4][4];
#pragma unroll
    for (int t = 0; t < 4; t++) {
        const float4* xp = (const float4*)(x + (size_t)(tok0 + t) * Dn);
#pragma unroll
        for (int q = 0; q < 4; q++) xr[t][q] = xp[lane + q * 32];
    }

    __shared__ float sg[4][Gn];
    __shared__ float snorm[4];

    for (int gg = 0; gg < 16; gg++) {
        int gi0 = warp * 32 + gg;
        int gi1 = gi0 + 16;
        const float4* w0 = (const float4*)(w + (size_t)gi0 * Dn);
        const float4* w1 = (const float4*)(w + (size_t)gi1 * Dn);
        float a0 = 0.f, a1 = 0.f, a2 = 0.f, a3 = 0.f;
        float b0 = 0.f, b1 = 0.f, b2 = 0.f, b3 = 0.f;
#pragma unroll
        for (int q = 0; q < 4; q++) {
            float4 wv0 = w0[lane + q * 32];
            float4 wv1 = w1[lane + q * 32];
            a0 += xr[0][q].x * wv0.x + xr[0][q].y * wv0.y + xr[0][q].z * wv0.z + xr[0][q].w * wv0.w;
            a1 += xr[1][q].x * wv0.x + xr[1][q].y * wv0.y + xr[1][q].z * wv0.z + xr[1][q].w * wv0.w;
            a2 += xr[2][q].x * wv0.x + xr[2][q].y * wv0.y + xr[2][q].z * wv0.z + xr[2][q].w * wv0.w;
            a3 += xr[3][q].x * wv0.x + xr[3][q].y * wv0.y + xr[3][q].z * wv0.z + xr[3][q].w * wv0.w;
            b0 += xr[0][q].x * wv1.x + xr[0][q].y * wv1.y + xr[0][q].z * wv1.z + xr[0][q].w * wv1.w;
            b1 += xr[1][q].x * wv1.x + xr[1][q].y * wv1.y + xr[1][q].z * wv1.z + xr[1][q].w * wv1.w;
            b2 += xr[2][q].x * wv1.x + xr[2][q].y * wv1.y + xr[2][q].z * wv1.z + xr[2][q].w * wv1.w;
            b3 += xr[3][q].x * wv1.x + xr[3][q].y * wv1.y + xr[3][q].z * wv1.z + xr[3][q].w * wv1.w;
        }
#pragma unroll
        for (int off = 16; off > 0; off >>= 1) {
            a0 += __shfl_down_sync(0xffffffffu, a0, off);
            a1 += __shfl_down_sync(0xffffffffu, a1, off);
            a2 += __shfl_down_sync(0xffffffffu, a2, off);
            a3 += __shfl_down_sync(0xffffffffu, a3, off);
            b0 += __shfl_down_sync(0xffffffffu, b0, off);
            b1 += __shfl_down_sync(0xffffffffu, b1, off);
            b2 += __shfl_down_sync(0xffffffffu, b2, off);
            b3 += __shfl_down_sync(0xffffffffu, b3, off);
        }
        if (lane == 0) {
            sg[0][gi0] = a0; sg[1][gi0] = a1; sg[2][gi0] = a2; sg[3][gi0] = a3;
            sg[0][gi1] = b0; sg[1][gi1] = b1; sg[2][gi1] = b2; sg[3][gi1] = b3;
        }
    }
    __syncthreads();

    if (threadIdx.x < 4) {
        int t = threadIdx.x;
        float ssum = 0.f;
        for (int gi = 0; gi < Gn; gi++) { float v = sg[t][gi]; ssum += v * v; }
        float nm = sqrtf(ssum);
        snorm[t] = nm;
        g_norms[tok0 + t] = nm;
    }
    __syncthreads();

    for (int idx = threadIdx.x; idx < 4 * Gn; idx += 64) {
        int t = idx >> 6, gi = idx & 63;
        g_gn[(size_t)(tok0 + t) * Gn + gi] = sg[t][gi] / fmaxf(snorm[t], EPSN);
    }
}

// ---------------- K1b: round-1 adjacent sims (coalesced, half-warp per sim) ----
__global__ void k_sim()
{
    int b = blockIdx.y;
    int warp = threadIdx.x >> 5;
    int lane = threadIdx.x & 31;
    int i = (blockIdx.x * 8 + warp) * 2 + (lane >> 4);
    int l = lane & 15;
    float d = 0.f;
    if (i < Ln - 1) {
        const float4* A = (const float4*)(g_gn + ((size_t)b * Ln + i) * Gn);
        float4 a = A[l], c = A[l + 16];   // next token row is contiguous
        d = a.x * c.x + a.y * c.y + a.z * c.z + a.w * c.w;
    }
    d += __shfl_down_sync(0xffffffffu, d, 8, 16);
    d += __shfl_down_sync(0xffffffffu, d, 4, 16);
    d += __shfl_down_sync(0xffffffffu, d, 2, 16);
    d += __shfl_down_sync(0xffffffffu, d, 1, 16);
    if (l == 0 && i < Ln - 1) g_sim[b * Ln + i] = d;
}

// ---------------- K2: merge plan simulation (1 block per batch) ----------------
__global__ __launch_bounds__(NT) void k_merge()
{
    const int b = blockIdx.x;
    const int tid = threadIdx.x;
    const int wid = tid >> 5;
    const int lane = tid & 31;
    const int half = lane >> 4;     // which half-warp
    const int l = lane & 15;        // lane within half-warp

    __shared__ float s_norm[Ln];
    __shared__ float s_sim[Ln];
    __shared__ unsigned short s_lo[Ln + 2];
    __shared__ unsigned char s_stat[Ln];   // 0 undecided, 1 accepted, 2 rejected, 3 selected
    __shared__ unsigned char s_dirty[Ln];
    __shared__ union UU {
        struct { int A[Ln]; int B[Ln]; } scan;
        unsigned long long key[Ln];
    } s_u;
    __shared__ int sh_n, sh_rem, sh_m;

    float* gnb   = g_gn + (size_t)b * Ln * Gn;
    float* coefb = g_coef + b * Ln;

    for (int i = tid; i < Ln; i += NT) {
        s_norm[i]  = g_norms[b * Ln + i];
        s_sim[i]   = g_sim[b * Ln + i];
        s_lo[i]    = (unsigned short)i;
        s_dirty[i] = 0;
        coefb[i]   = 1.0f;
    }
    if (tid == 0) { s_lo[Ln] = (unsigned short)Ln; sh_n = Ln; sh_rem = Ln - Tn; }
    __syncthreads();

    for (int round = 0; round < 24; round++) {
        int n = sh_n, rem = sh_rem;
        if (rem <= 0 || n < 2) break;

        // 1) recompute dirty sims (half-warp cooperative, coalesced row loads)
        for (int base = wid * 2; base < n - 1; base += NW * 2) {
            int i = base + half;
            bool valid = (i < n - 1) && s_dirty[i];
            float d = 0.f;
            if (valid) {
                const float4* Ap = (const float4*)(gnb + (size_t)s_lo[i] * Gn);
                const float4* Bp = (const float4*)(gnb + (size_t)s_lo[i + 1] * Gn);
                float4 a = Ap[l], c = Bp[l];
                d = a.x * c.x + a.y * c.y + a.z * c.z + a.w * c.w;
            }
            d += __shfl_down_sync(0xffffffffu, d, 8, 16);
            d += __shfl_down_sync(0xffffffffu, d, 4, 16);
            d += __shfl_down_sync(0xffffffffu, d, 2, 16);
            d += __shfl_down_sync(0xffffffffu, d, 1, 16);
            if (valid && l == 0) { s_sim[i] = d; s_dirty[i] = 0; }
        }
        for (int i = tid; i < n - 1; i += NT) s_stat[i] = 0;
        __syncthreads();

        // 2) uncapped greedy matching via priority-local-max fixed point
        //    (one barrier per iteration via __syncthreads_count, no atomics)
        while (1) {
            int und = 0;
            for (int i = tid; i < n - 1; i += NT) {
                if (s_stat[i] == 0) {
                    float si = s_sim[i];
                    bool hiL = (i > 0) && (s_sim[i - 1] >= si);          // left wins ties
                    bool hiR = (i + 1 < n - 1) && (s_sim[i + 1] > si);
                    unsigned char a = hiL ? s_stat[i - 1] : (unsigned char)2;
                    unsigned char c = hiR ? s_stat[i + 1] : (unsigned char)2;
                    if (a == 2 && c == 2) s_stat[i] = 1;
                    else if (a == 1 || c == 1) s_stat[i] = 2;
                    else und++;
                }
            }
            if (__syncthreads_count(und) == 0) break;
        }

        // 3) |M| count (once per round)
        if (tid == 0) sh_m = 0;
        __syncthreads();
        {
            int lm = 0;
            for (int i = tid; i < n - 1; i += NT) lm += (s_stat[i] == 1);
#pragma unroll
            for (int off = 16; off > 0; off >>= 1) lm += __shfl_down_sync(0xffffffffu, lm, off);
            if (lane == 0) atomicAdd(&sh_m, lm);
        }
        __syncthreads();
        int m = sh_m;
        int r_step = min(rem, n >> 1);
        int cnt = min(m, r_step);

        // 4) selection: top-r_step of accepted (only when cap binds)
        if (m > r_step) {
            int P = 1; while (P < n - 1) P <<= 1;
            for (int i = tid; i < P; i += NT) {
                unsigned long long key = 0ull;
                if (i < n - 1 && s_stat[i] == 1) {
                    unsigned int u = __float_as_uint(s_sim[i]);
                    unsigned int sk = (u & 0x80000000u) ? ~u : (u | 0x80000000u);
                    key = ((unsigned long long)sk << 16) | (unsigned int)(Ln - 1 - i);
                }
                s_u.key[i] = key;
            }
            __syncthreads();
            for (int k = 2; k <= P; k <<= 1) {
                for (int j = k >> 1; j > 0; j >>= 1) {
                    for (int i = tid; i < P; i += NT) {
                        int ixj = i ^ j;
                        if (ixj > i) {
                            unsigned long long a = s_u.key[i], c = s_u.key[ixj];
                            bool dir = ((i & k) == 0);
                            bool sw = dir ? (a < c) : (a > c);
                            if (sw) { s_u.key[i] = c; s_u.key[ixj] = a; }
                        }
                    }
                    __syncthreads();
                }
            }
            for (int r = tid; r < r_step; r += NT) {
                int idx = Ln - 1 - (int)(s_u.key[r] & 0xFFFFull);
                s_stat[idx] = 3;
            }
            __syncthreads();
        } else {
            for (int i = tid; i < n - 1; i += NT) if (s_stat[i] == 1) s_stat[i] = 3;
            __syncthreads();
        }

        // 5) apply merges (half-warp cooperative; pairs non-overlapping -> race-free)
        for (int base = wid * 2; base < n - 1; base += NW * 2) {
            int i = base + half;
            bool valid = (i < n - 1) && (s_stat[i] == 3);
            float wi = 0.f, wj = 0.f, tot = 1.f;
            int ta = 0, tb = 0, tc = 0;
            float4 a = make_float4(0.f, 0.f, 0.f, 0.f);
            float4 c = a;
            float4* Ap = 0;
            if (valid) {
                wi = s_norm[i]; wj = s_norm[i + 1];
                tot = wi + wj + EPSW;
                ta = s_lo[i]; tb = s_lo[i + 1]; tc = s_lo[i + 2];
                Ap = (float4*)(gnb + (size_t)ta * Gn);
                const float4* Bp = (const float4*)(gnb + (size_t)tb * Gn);
                a = Ap[l]; c = Bp[l];
            }
            float mx = (wi * a.x + wj * c.x) / tot;
            float my = (wi * a.y + wj * c.y) / tot;
            float mz = (wi * a.z + wj * c.z) / tot;
            float mw = (wi * a.w + wj * c.w) / tot;
            float ssq = mx * mx + my * my + mz * mz + mw * mw;
            ssq += __shfl_xor_sync(0xffffffffu, ssq, 8, 16);
            ssq += __shfl_xor_sync(0xffffffffu, ssq, 4, 16);
            ssq += __shfl_xor_sync(0xffffffffu, ssq, 2, 16);
            ssq += __shfl_xor_sync(0xffffffffu, ssq, 1, 16);
            if (valid) {
                float inv = 1.f / fmaxf(sqrtf(ssq), EPSN);
                float4 o; o.x = mx * inv; o.y = my * inv; o.z = mz * inv; o.w = mw * inv;
                Ap[l] = o;
                float fa = wi / tot, fb = wj / tot;
                for (int t = ta + l; t < tb; t += 16) coefb[t] *= fa;
                for (int t = tb + l; t < tc; t += 16) coefb[t] *= fb;
                if (l == 0) {
                    s_norm[i] = (wi + wj) * 0.5f;
                    s_dirty[i] = 1;
                    if (i > 0) s_dirty[i - 1] = 1;
                }
            }
        }
        __syncthreads();

        // 6) compaction (drop 'second' slots): Hillis-Steele scan + 2-phase move
        int* Aq = s_u.scan.A;
        int* Bq = s_u.scan.B;
        for (int j = tid; j < n; j += NT)
            Aq[j] = (j > 0 && s_stat[j - 1] == 3) ? 0 : 1;
        __syncthreads();
        for (int off = 1; off < n; off <<= 1) {
            for (int j = tid; j < n; j += NT)
                Bq[j] = Aq[j] + ((j >= off) ? Aq[j - off] : 0);
            __syncthreads();
            int* tp = Aq; Aq = Bq; Bq = tp;
        }
        // phase 1: gather into registers
        float rn[4], rs[4];
        unsigned short rl[4];
        unsigned char rd[4];
        int rp[4];
        int myk = 0;
        for (int j = tid; j < n; j += NT) {
            if (!(j > 0 && s_stat[j - 1] == 3)) {
                rp[myk] = Aq[j] - 1;
                rn[myk] = s_norm[j];
                rs[myk] = s_sim[j];
                rl[myk] = s_lo[j];
                rd[myk] = s_dirty[j];
                myk++;
            }
        }
        __syncthreads();
        // phase 2: scatter
        for (int k = 0; k < myk; k++) {
            s_norm[rp[k]]  = rn[k];
            s_sim[rp[k]]   = rs[k];
            s_lo[rp[k]]    = rl[k];
            s_dirty[rp[k]] = rd[k];
        }
        int newn = n - cnt;
        if (tid == 0) { sh_n = newn; sh_rem = rem - cnt; }
        __syncthreads();
        if (tid == 0) s_lo[newn] = (unsigned short)Ln;
        __syncthreads();
    }

    for (int k = tid; k <= Tn; k += NT) g_lo[b * (Tn + 1) + k] = (int)s_lo[k];
}

// ---------------- K3: apply plan (bandwidth-bound) ----------------
__global__ void k_apply(const float* __restrict__ x, const float* __restrict__ s,
                        float* __restrict__ out)
{
    int kslot = blockIdx.x;
    int chunk = blockIdx.y;
    int b = blockIdx.z;
    int lo = g_lo[b * (Tn + 1) + kslot];
    int hi = g_lo[b * (Tn + 1) + kslot + 1];
    int t4 = threadIdx.x;  // 128 threads x float4 = 512 floats

    if (chunk == 0) {
        float4 acc = make_float4(0.f, 0.f, 0.f, 0.f);
#pragma unroll 2
        for (int t = lo; t < hi; t++) {
            float c = g_coef[b * Ln + t];
            float4 v = ((const float4*)(x + ((size_t)b * Ln + t) * Dn))[t4];
            acc.x += c * v.x; acc.y += c * v.y; acc.z += c * v.z; acc.w += c * v.w;
        }
        ((float4*)(out + ((size_t)b * Tn + kslot) * Dn))[t4] = acc;
    } else {
        int c0 = (chunk - 1) * 512;
        float4 acc = make_float4(0.f, 0.f, 0.f, 0.f);
#pragma unroll 2
        for (int t = lo; t < hi; t++) {
            float4 v = ((const float4*)(s + ((size_t)b * Ln + t) * Nn + c0))[t4];
            acc.x += v.x; acc.y += v.y; acc.z += v.z; acc.w += v.w;
        }
        ((float4*)(out + (size_t)Bn * Tn * Dn + ((size_t)b * Tn + kslot) * Nn + c0))[t4] = acc;
    }
}

// ---------------- launch ----------------
extern "C" void kernel_launch(void* const* d_in, const int* in_sizes, int n_in,
                              void* d_out, int out_size)
{
    const float* x = (const float*)d_in[0];
    const float* src = (const float*)d_in[1];
    const float* w = (const float*)d_in[2];
    float* out = (float*)d_out;

    k_gn<<<Bn * Ln / 4, 64>>>(x, w);
    k_sim<<<dim3(128, Bn), 256>>>();
    k_merge<<<Bn, NT>>>();
    dim3 g3(Tn, 1 + Nn / 512, Bn);
    k_apply<<<g3, 128>>>(x, src, out);
}

// round 3
// speedup vs baseline: 1.4585x; 1.4585x over previous
#include <cuda_runtime.h>
#include <math.h>

#define Bn 2
#define Ln 2048
#define Dn 512
#define Nn 4096
#define Gn 64
#define Tn 512
#define EPSN 1e-12f
#define EPSW 1e-8f
#define NT 1024
#define NW 32

// ---------------- scratch (static device globals; no allocation) ----------------
__device__ __align__(256) float g_gn[Bn * Ln * Gn];   // unit group vectors, token storage
__device__ float g_norms[Bn * Ln];
__device__ float g_sim[Bn * Ln];                      // round-1 adjacent sims
__device__ float g_coef[Bn * Ln];                     // per-original-token x coefficient
__device__ int   g_lo[Bn * (Tn + 1)];                 // final slot range starts

// ---------------- K1: g = x @ w^T, norms, gn (round-1 version, known good) -----
__global__ void k_gn(const float* __restrict__ x, const float* __restrict__ w)
{
    int tok0 = blockIdx.x * 4;
    int warp = threadIdx.x >> 5;
    int lane = threadIdx.x & 31;

    float4 xr[4][4];
#pragma unroll
    for (int t = 0; t < 4; t++) {
        const float4* xp = (const float4*)(x + (size_t)(tok0 + t) * Dn);
#pragma unroll
        for (int q = 0; q < 4; q++) xr[t][q] = xp[lane + q * 32];
    }

    __shared__ float sg[4][Gn];
    __shared__ float snorm[4];

    for (int gg = 0; gg < 32; gg++) {
        int gi = warp * 32 + gg;
        const float4* wp = (const float4*)(w + (size_t)gi * Dn);
        float a0 = 0.f, a1 = 0.f, a2 = 0.f, a3 = 0.f;
#pragma unroll
        for (int q = 0; q < 4; q++) {
            float4 wv = wp[lane + q * 32];
            a0 += xr[0][q].x * wv.x + xr[0][q].y * wv.y + xr[0][q].z * wv.z + xr[0][q].w * wv.w;
            a1 += xr[1][q].x * wv.x + xr[1][q].y * wv.y + xr[1][q].z * wv.z + xr[1][q].w * wv.w;
            a2 += xr[2][q].x * wv.x + xr[2][q].y * wv.y + xr[2][q].z * wv.z + xr[2][q].w * wv.w;
            a3 += xr[3][q].x * wv.x + xr[3][q].y * wv.y + xr[3][q].z * wv.z + xr[3][q].w * wv.w;
        }
#pragma unroll
        for (int off = 16; off > 0; off >>= 1) {
            a0 += __shfl_down_sync(0xffffffffu, a0, off);
            a1 += __shfl_down_sync(0xffffffffu, a1, off);
            a2 += __shfl_down_sync(0xffffffffu, a2, off);
            a3 += __shfl_down_sync(0xffffffffu, a3, off);
        }
        if (lane == 0) { sg[0][gi] = a0; sg[1][gi] = a1; sg[2][gi] = a2; sg[3][gi] = a3; }
    }
    __syncthreads();

    if (threadIdx.x < 4) {
        int t = threadIdx.x;
        float ssum = 0.f;
        for (int gi = 0; gi < Gn; gi++) { float v = sg[t][gi]; ssum += v * v; }
        float nm = sqrtf(ssum);
        snorm[t] = nm;
        g_norms[tok0 + t] = nm;
    }
    __syncthreads();

    for (int idx = threadIdx.x; idx < 4 * Gn; idx += 64) {
        int t = idx >> 6, gi = idx & 63;
        g_gn[(size_t)(tok0 + t) * Gn + gi] = sg[t][gi] / fmaxf(snorm[t], EPSN);
    }
}

// ---------------- K1b: round-1 adjacent sims (coalesced, half-warp per sim) ----
__global__ void k_sim()
{
    int b = blockIdx.y;
    int warp = threadIdx.x >> 5;
    int lane = threadIdx.x & 31;
    int i = (blockIdx.x * 8 + warp) * 2 + (lane >> 4);
    int l = lane & 15;
    float d = 0.f;
    if (i < Ln - 1) {
        const float4* A = (const float4*)(g_gn + ((size_t)b * Ln + i) * Gn);
        float4 a = A[l], c = A[l + 16];
        d = a.x * c.x + a.y * c.y + a.z * c.z + a.w * c.w;
    }
    d += __shfl_down_sync(0xffffffffu, d, 8, 16);
    d += __shfl_down_sync(0xffffffffu, d, 4, 16);
    d += __shfl_down_sync(0xffffffffu, d, 2, 16);
    d += __shfl_down_sync(0xffffffffu, d, 1, 16);
    if (l == 0 && i < Ln - 1) g_sim[b * Ln + i] = d;
}

// ---------------- K2: merge plan simulation (1 block per batch) ----------------
__global__ __launch_bounds__(NT) void k_merge()
{
    const int b = blockIdx.x;
    const int tid = threadIdx.x;
    const int wid = tid >> 5;
    const int lane = tid & 31;
    const int half = lane >> 4;
    const int l = lane & 15;

    __shared__ float s_norm[Ln];
    __shared__ float s_sim[Ln];
    __shared__ unsigned short s_lo[Ln + 2];
    __shared__ unsigned char s_stat[Ln];   // 0 undecided, 1 accepted, 2 rejected, 3 selected
    __shared__ unsigned char s_dirty[Ln];
    __shared__ union UU {
        struct { int A[Ln]; int B[Ln]; } scan;
        unsigned long long key[Ln];
    } s_u;
    __shared__ int sh_n, sh_rem, sh_m;

    float* gnb   = g_gn + (size_t)b * Ln * Gn;
    float* coefb = g_coef + b * Ln;

    for (int i = tid; i < Ln; i += NT) {
        s_norm[i]  = g_norms[b * Ln + i];
        s_sim[i]   = g_sim[b * Ln + i];
        s_lo[i]    = (unsigned short)i;
        s_dirty[i] = 0;
        coefb[i]   = 1.0f;
    }
    if (tid == 0) { s_lo[Ln] = (unsigned short)Ln; sh_n = Ln; sh_rem = Ln - Tn; }
    __syncthreads();

    for (int round = 0; round < 24; round++) {
        int n = sh_n, rem = sh_rem;
        if (rem <= 0 || n < 2) break;

        // 1) recompute dirty sims (half-warp cooperative, coalesced row loads)
        for (int base = wid * 2; base < n - 1; base += NW * 2) {
            int i = base + half;
            bool valid = (i < n - 1) && s_dirty[i];
            float d = 0.f;
            if (valid) {
                const float4* Ap = (const float4*)(gnb + (size_t)s_lo[i] * Gn);
                const float4* Bp = (const float4*)(gnb + (size_t)s_lo[i + 1] * Gn);
                float4 a = Ap[l], c = Bp[l];
                d = a.x * c.x + a.y * c.y + a.z * c.z + a.w * c.w;
            }
            d += __shfl_down_sync(0xffffffffu, d, 8, 16);
            d += __shfl_down_sync(0xffffffffu, d, 4, 16);
            d += __shfl_down_sync(0xffffffffu, d, 2, 16);
            d += __shfl_down_sync(0xffffffffu, d, 1, 16);
            if (valid && l == 0) { s_sim[i] = d; s_dirty[i] = 0; }
        }
        for (int i = tid; i < n - 1; i += NT) s_stat[i] = 0;
        __syncthreads();

        // 2) uncapped greedy matching via priority-local-max fixed point
        while (1) {
            int und = 0;
            for (int i = tid; i < n - 1; i += NT) {
                if (s_stat[i] == 0) {
                    float si = s_sim[i];
                    bool hiL = (i > 0) && (s_sim[i - 1] >= si);          // left wins ties
                    bool hiR = (i + 1 < n - 1) && (s_sim[i + 1] > si);
                    unsigned char a = hiL ? s_stat[i - 1] : (unsigned char)2;
                    unsigned char c = hiR ? s_stat[i + 1] : (unsigned char)2;
                    if (a == 2 && c == 2) s_stat[i] = 1;
                    else if (a == 1 || c == 1) s_stat[i] = 2;
                    else und++;
                }
            }
            if (__syncthreads_count(und) == 0) break;
        }

        // 3) |M| count
        if (tid == 0) sh_m = 0;
        __syncthreads();
        {
            int lm = 0;
            for (int i = tid; i < n - 1; i += NT) lm += (s_stat[i] == 1);
#pragma unroll
            for (int off = 16; off > 0; off >>= 1) lm += __shfl_down_sync(0xffffffffu, lm, off);
            if (lane == 0) atomicAdd(&sh_m, lm);
        }
        __syncthreads();
        int m = sh_m;
        int r_step = min(rem, n >> 1);
        int cnt = min(m, r_step);

        // 4) selection: top-r_step of accepted (only when cap binds)
        if (m > r_step) {
            int P = 1; while (P < n - 1) P <<= 1;
            for (int i = tid; i < P; i += NT) {
                unsigned long long key = 0ull;
                if (i < n - 1 && s_stat[i] == 1) {
                    unsigned int u = __float_as_uint(s_sim[i]);
                    unsigned int sk = (u & 0x80000000u) ? ~u : (u | 0x80000000u);
                    key = ((unsigned long long)sk << 16) | (unsigned int)(Ln - 1 - i);
                }
                s_u.key[i] = key;
            }
            __syncthreads();
            for (int k = 2; k <= P; k <<= 1) {
                for (int j = k >> 1; j > 0; j >>= 1) {
                    for (int i = tid; i < P; i += NT) {
                        int ixj = i ^ j;
                        if (ixj > i) {
                            unsigned long long a = s_u.key[i], c = s_u.key[ixj];
                            bool dir = ((i & k) == 0);
                            bool sw = dir ? (a < c) : (a > c);
                            if (sw) { s_u.key[i] = c; s_u.key[ixj] = a; }
                        }
                    }
                    __syncthreads();
                }
            }
            for (int r = tid; r < r_step; r += NT) {
                int idx = Ln - 1 - (int)(s_u.key[r] & 0xFFFFull);
                s_stat[idx] = 3;
            }
            __syncthreads();
        } else {
            for (int i = tid; i < n - 1; i += NT) if (s_stat[i] == 1) s_stat[i] = 3;
            __syncthreads();
        }

        // 5) apply merges (half-warp cooperative; pairs non-overlapping -> race-free)
        for (int base = wid * 2; base < n - 1; base += NW * 2) {
            int i = base + half;
            bool valid = (i < n - 1) && (s_stat[i] == 3);
            float wi = 0.f, wj = 0.f, tot = 1.f;
            int ta = 0, tb = 0, tc = 0;
            float4 a = make_float4(0.f, 0.f, 0.f, 0.f);
            float4 c = a;
            float4* Ap = 0;
            if (valid) {
                wi = s_norm[i]; wj = s_norm[i + 1];
                tot = wi + wj + EPSW;
                ta = s_lo[i]; tb = s_lo[i + 1]; tc = s_lo[i + 2];
                Ap = (float4*)(gnb + (size_t)ta * Gn);
                const float4* Bp = (const float4*)(gnb + (size_t)tb * Gn);
                a = Ap[l]; c = Bp[l];
            }
            float mx = (wi * a.x + wj * c.x) / tot;
            float my = (wi * a.y + wj * c.y) / tot;
            float mz = (wi * a.z + wj * c.z) / tot;
            float mw = (wi * a.w + wj * c.w) / tot;
            float ssq = mx * mx + my * my + mz * mz + mw * mw;
            ssq += __shfl_xor_sync(0xffffffffu, ssq, 8, 16);
            ssq += __shfl_xor_sync(0xffffffffu, ssq, 4, 16);
            ssq += __shfl_xor_sync(0xffffffffu, ssq, 2, 16);
            ssq += __shfl_xor_sync(0xffffffffu, ssq, 1, 16);
            if (valid) {
                float inv = 1.f / fmaxf(sqrtf(ssq), EPSN);
                float4 o; o.x = mx * inv; o.y = my * inv; o.z = mz * inv; o.w = mw * inv;
                Ap[l] = o;
                float fa = wi / tot, fb = wj / tot;
                for (int t = ta + l; t < tb; t += 16) coefb[t] *= fa;
                for (int t = tb + l; t < tc; t += 16) coefb[t] *= fb;
                if (l == 0) {
                    s_norm[i] = (wi + wj) * 0.5f;
                    s_dirty[i] = 1;
                    if (i > 0) s_dirty[i - 1] = 1;
                }
            }
        }
        __syncthreads();

        // 6) compaction (drop 'second' slots): Hillis-Steele scan + 2-phase move
        int* Aq = s_u.scan.A;
        int* Bq = s_u.scan.B;
        for (int j = tid; j < n; j += NT)
            Aq[j] = (j > 0 && s_stat[j - 1] == 3) ? 0 : 1;
        __syncthreads();
        for (int off = 1; off < n; off <<= 1) {
            for (int j = tid; j < n; j += NT)
                Bq[j] = Aq[j] + ((j >= off) ? Aq[j - off] : 0);
            __syncthreads();
            int* tp = Aq; Aq = Bq; Bq = tp;
        }
        float rn[2], rs[2];
        unsigned short rl[2];
        unsigned char rd[2];
        int rp[2];
        int myk = 0;
        for (int j = tid; j < n; j += NT) {
            if (!(j > 0 && s_stat[j - 1] == 3)) {
                rp[myk] = Aq[j] - 1;
                rn[myk] = s_norm[j];
                rs[myk] = s_sim[j];
                rl[myk] = s_lo[j];
                rd[myk] = s_dirty[j];
                myk++;
            }
        }
        __syncthreads();
        for (int k = 0; k < myk; k++) {
            s_norm[rp[k]]  = rn[k];
            s_sim[rp[k]]   = rs[k];
            s_lo[rp[k]]    = rl[k];
            s_dirty[rp[k]] = rd[k];
        }
        int newn = n - cnt;
        if (tid == 0) { sh_n = newn; sh_rem = rem - cnt; }
        __syncthreads();
        if (tid == 0) s_lo[newn] = (unsigned short)Ln;
        __syncthreads();
    }

    for (int k = tid; k <= Tn; k += NT) g_lo[b * (Tn + 1) + k] = (int)s_lo[k];
}

// ---------------- K3: apply plan (bandwidth-bound, MLP-4 unroll) ----------------
__global__ void k_apply(const float* __restrict__ x, const float* __restrict__ s,
                        float* __restrict__ out)
{
    int kslot = blockIdx.x;
    int chunk = blockIdx.y;
    int b = blockIdx.z;
    int lo = g_lo[b * (Tn + 1) + kslot];
    int hi = g_lo[b * (Tn + 1) + kslot + 1];
    int t4 = threadIdx.x;  // 128 threads x float4 = 512 floats

    float4 a0 = make_float4(0.f, 0.f, 0.f, 0.f);
    float4 a1 = a0, a2 = a0, a3 = a0;

    if (chunk == 0) {
        const float* cb = g_coef + b * Ln;
        int t = lo;
        for (; t + 4 <= hi; t += 4) {
            float c0 = cb[t], c1 = cb[t + 1], c2 = cb[t + 2], c3 = cb[t + 3];
            float4 v0 = ((const float4*)(x + ((size_t)b * Ln + t)     * Dn))[t4];
            float4 v1 = ((const float4*)(x + ((size_t)b * Ln + t + 1) * Dn))[t4];
            float4 v2 = ((const float4*)(x + ((size_t)b * Ln + t + 2) * Dn))[t4];
            float4 v3 = ((const float4*)(x + ((size_t)b * Ln + t + 3) * Dn))[t4];
            a0.x += c0 * v0.x; a0.y += c0 * v0.y; a0.z += c0 * v0.z; a0.w += c0 * v0.w;
            a1.x += c1 * v1.x; a1.y += c1 * v1.y; a1.z += c1 * v1.z; a1.w += c1 * v1.w;
            a2.x += c2 * v2.x; a2.y += c2 * v2.y; a2.z += c2 * v2.z; a2.w += c2 * v2.w;
            a3.x += c3 * v3.x; a3.y += c3 * v3.y; a3.z += c3 * v3.z; a3.w += c3 * v3.w;
        }
        for (; t < hi; t++) {
            float c = cb[t];
            float4 v = ((const float4*)(x + ((size_t)b * Ln + t) * Dn))[t4];
            a0.x += c * v.x; a0.y += c * v.y; a0.z += c * v.z; a0.w += c * v.w;
        }
        float4 r;
        r.x = (a0.x + a1.x) + (a2.x + a3.x);
        r.y = (a0.y + a1.y) + (a2.y + a3.y);
        r.z = (a0.z + a1.z) + (a2.z + a3.z);
        r.w = (a0.w + a1.w) + (a2.w + a3.w);
        ((float4*)(out + ((size_t)b * Tn + kslot) * Dn))[t4] = r;
    } else {
        int c0 = (chunk - 1) * 512;
        int t = lo;
        for (; t + 4 <= hi; t += 4) {
            float4 v0 = ((const float4*)(s + ((size_t)b * Ln + t)     * Nn + c0))[t4];
            float4 v1 = ((const float4*)(s + ((size_t)b * Ln + t + 1) * Nn + c0))[t4];
            float4 v2 = ((const float4*)(s + ((size_t)b * Ln + t + 2) * Nn + c0))[t4];
            float4 v3 = ((const float4*)(s + ((size_t)b * Ln + t + 3) * Nn + c0))[t4];
            a0.x += v0.x; a0.y += v0.y; a0.z += v0.z; a0.w += v0.w;
            a1.x += v1.x; a1.y += v1.y; a1.z += v1.z; a1.w += v1.w;
            a2.x += v2.x; a2.y += v2.y; a2.z += v2.z; a2.w += v2.w;
            a3.x += v3.x; a3.y += v3.y; a3.z += v3.z; a3.w += v3.w;
        }
        for (; t < hi; t++) {
            float4 v = ((const float4*)(s + ((size_t)b * Ln + t) * Nn + c0))[t4];
            a0.x += v.x; a0.y += v.y; a0.z += v.z; a0.w += v.w;
        }
        float4 r;
        r.x = (a0.x + a1.x) + (a2.x + a3.x);
        r.y = (a0.y + a1.y) + (a2.y + a3.y);
        r.z = (a0.z + a1.z) + (a2.z + a3.z);
        r.w = (a0.w + a1.w) + (a2.w + a3.w);
        ((float4*)(out + (size_t)Bn * Tn * Dn + ((size_t)b * Tn + kslot) * Nn + c0))[t4] = r;
    }
}

// ---------------- launch ----------------
extern "C" void kernel_launch(void* const* d_in, const int* in_sizes, int n_in,
                              void* d_out, int out_size)
{
    const float* x = (const float*)d_in[0];
    const float* src = (const float*)d_in[1];
    const float* w = (const float*)d_in[2];
    float* out = (float*)d_out;

    k_gn<<<Bn * Ln / 4, 64>>>(x, w);
    k_sim<<<dim3(128, Bn), 256>>>();
    k_merge<<<Bn, NT>>>();
    dim3 g3(Tn, 1 + Nn / 512, Bn);
    k_apply<<<g3, 128>>>(x, src, out);
}